// round 3
// baseline (speedup 1.0000x reference)
#include <cuda_runtime.h>
#include <cuda_bf16.h>
#include <math.h>

// ---------------------------------------------------------------------------
// VQ-VAE forward on GB300 (sm_103a). Round 3: replicate jax fp32 dist rounding.
//   h1   = relu(x @ W1 + b1)            [32768, 512]
//   z_e  = h1 @ W2 + b2                 [32768, 1024]  -> output region 2
//   VQ   : dist = fl(fl(z2 - 2*cross) + e2), argmin (first-min tie rule)
//   emb  = E[:, idx]                    [32768, 1024]  -> output region 3
//   h3   = relu(emb @ W3 + b3)
//   recon= tanh(h3 @ W4 + b4)          -> output region 1
// Output layout: recon | z_e | emb  (fp32, concatenated)
// ---------------------------------------------------------------------------

#define Bsz    32768
#define IN_DIM 784
#define H0     512
#define H1     1024
#define Kc     128    // codebook entries
#define Dd     128    // embedding dim
#define Nn     8      // slots per sample

// Scratch (allocation-free rule: __device__ globals). 128 MB total.
__device__ __align__(16) float g_h1[Bsz * H0];
__device__ __align__(16) float g_h3[Bsz * H0];

// ---------------------------------------------------------------------------
// Tiled SGEMM: C[M,N] = act(A[M,K] @ W[K,N] + bias)
// BM=128, BN=128, BK=8, 256 threads, 8x8 microtile.
// Accumulation is strictly k-ascending FFMA per output element (this ordering
// is load-bearing for VQ index reproducibility -- do not reassociate).
// ACT: 0=none, 1=relu, 2=tanh
// ---------------------------------------------------------------------------
template <int ACT>
__global__ __launch_bounds__(256, 2)
void gemm_kernel(const float* __restrict__ A, const float* __restrict__ W,
                 const float* __restrict__ bias, float* __restrict__ C,
                 int M, int N, int K)
{
    __shared__ float As[8][128];
    __shared__ float Bs[8][128];

    const int tid = threadIdx.x;
    const int m0  = blockIdx.y * 128;
    const int n0  = blockIdx.x * 128;

    const int tx = tid & 15;          // n dir
    const int ty = tid >> 4;          // m dir
    const int row0 = ty * 8;
    const int col0 = tx * 8;

    const int a_r = tid >> 1;         // A row within tile
    const int a_q = (tid & 1) * 4;    // A col quad
    const int b_r = tid >> 5;         // B k-row
    const int b_q = (tid & 31) * 4;   // B n within tile

    float acc[8][8];
#pragma unroll
    for (int i = 0; i < 8; ++i)
#pragma unroll
        for (int j = 0; j < 8; ++j) acc[i][j] = 0.0f;

    const int nsteps = K >> 3;
    for (int s = 0; s < nsteps; ++s) {
        const int k0 = s << 3;

        float4 av = *reinterpret_cast<const float4*>(
            &A[(size_t)(m0 + a_r) * K + k0 + a_q]);
        As[a_q + 0][a_r] = av.x;
        As[a_q + 1][a_r] = av.y;
        As[a_q + 2][a_r] = av.z;
        As[a_q + 3][a_r] = av.w;

        float4 bv = make_float4(0.f, 0.f, 0.f, 0.f);
        if (n0 + b_q < N)
            bv = *reinterpret_cast<const float4*>(
                &W[(size_t)(k0 + b_r) * N + n0 + b_q]);
        *reinterpret_cast<float4*>(&Bs[b_r][b_q]) = bv;

        __syncthreads();

#pragma unroll
        for (int kk = 0; kk < 8; ++kk) {
            float a[8], b[8];
            *reinterpret_cast<float4*>(&a[0]) = *reinterpret_cast<const float4*>(&As[kk][row0]);
            *reinterpret_cast<float4*>(&a[4]) = *reinterpret_cast<const float4*>(&As[kk][row0 + 4]);
            *reinterpret_cast<float4*>(&b[0]) = *reinterpret_cast<const float4*>(&Bs[kk][col0]);
            *reinterpret_cast<float4*>(&b[4]) = *reinterpret_cast<const float4*>(&Bs[kk][col0 + 4]);
#pragma unroll
            for (int i = 0; i < 8; ++i)
#pragma unroll
                for (int j = 0; j < 8; ++j)
                    acc[i][j] = fmaf(a[i], b[j], acc[i][j]);
        }
        __syncthreads();
    }

#pragma unroll
    for (int i = 0; i < 8; ++i) {
        const size_t rowoff = (size_t)(m0 + row0 + i) * N;
#pragma unroll
        for (int j = 0; j < 8; ++j) {
            const int n = n0 + col0 + j;
            if (n < N) {
                float c = acc[i][j];
                if (bias) c = __fadd_rn(c, bias[n]);
                if (ACT == 1) c = fmaxf(c, 0.0f);
                if (ACT == 2) c = tanhf(c);
                C[rowoff + n] = c;
            }
        }
    }
}

// ---------------------------------------------------------------------------
// Fused VQ, jax-rounding-replicated.
// One block = 8 samples; E (64KB) + z (32KB) + e2 staged in shared.
// One warp per sample; lane l owns codes k = 4l..4l+3 for all 8 slots.
//   cross[n][k]: d-ascending FFMA chain   (matches XLA dot emitter)
//   z2[n], e2[k]: d-ascending fp32 mul+add, NO fma (matches XLA reduce emitter)
//   dist = fl(fl(z2 - 2*cross) + e2)      (matches jnp elementwise order;
//          fmaf(-2,c,z2) == fl(z2-2c) exactly since 2c is exact)
// Tie rule: first minimum (matches jnp.argmin).
// Writes emb[b, d*8+n] = E[d, idx[b,n]] directly (emb layout == z_q).
// ---------------------------------------------------------------------------
#define VQ_SAMPLES 8
#define VQ_SMEM ((Kc * Dd + VQ_SAMPLES * H1 + Kc) * (int)sizeof(float))

__global__ __launch_bounds__(256, 2)
void vq_kernel(const float* __restrict__ z_e, const float* __restrict__ E,
               float* __restrict__ emb)
{
    extern __shared__ float sh[];
    float* E_sh  = sh;                       // [Dd][Kc] = 16384 floats
    float* z_sh  = sh + Kc * Dd;             // [8][1024]
    float* e2_sh = z_sh + VQ_SAMPLES * H1;   // [Kc]

    const int tid  = threadIdx.x;
    const int warp = tid >> 5;
    const int lane = tid & 31;
    const size_t b0 = (size_t)blockIdx.x * VQ_SAMPLES;

    // Load E [D,K] row-major: straight copy, coalesced.
#pragma unroll
    for (int i = 0; i < (Kc * Dd / 4) / 256; ++i)
        reinterpret_cast<float4*>(E_sh)[tid + i * 256] =
            reinterpret_cast<const float4*>(E)[tid + i * 256];

    // Load 8 samples of z: coalesced.
#pragma unroll
    for (int i = 0; i < (VQ_SAMPLES * H1 / 4) / 256; ++i)
        reinterpret_cast<float4*>(z_sh)[tid + i * 256] =
            reinterpret_cast<const float4*>(z_e + b0 * H1)[tid + i * 256];
    __syncthreads();

    // e2[k] = sum_d E[d][k]^2 : d-ascending, separate mul/add (no FMA).
    if (tid < Kc) {
        float s = 0.f;
#pragma unroll 16
        for (int d = 0; d < Dd; ++d) {
            float v = E_sh[d * Kc + tid];
            s = __fadd_rn(s, __fmul_rn(v, v));
        }
        e2_sh[tid] = s;
    }
    __syncthreads();

    const int s = warp;                      // local sample
    const float* zrow = z_sh + s * H1;

    // z2[n] = sum_d z[d,n]^2 : d-ascending, separate mul/add (no FMA).
    float s2 = 0.f;
    {
        const int n = lane & 7;              // lanes 0..7 produce the 8 slots
#pragma unroll 16
        for (int d = 0; d < Dd; ++d) {
            float v = zrow[d * 8 + n];
            s2 = __fadd_rn(s2, __fmul_rn(v, v));
        }
    }
    float z2v[Nn];
#pragma unroll
    for (int n = 0; n < Nn; ++n)
        z2v[n] = __shfl_sync(0xFFFFFFFFu, s2, n);

    // cross[n][j]: d-ascending FFMA chains.
    float acc[Nn][4];
#pragma unroll
    for (int n = 0; n < Nn; ++n)
#pragma unroll
        for (int j = 0; j < 4; ++j) acc[n][j] = 0.f;

#pragma unroll 4
    for (int d = 0; d < Dd; ++d) {
        float4 ev = *reinterpret_cast<const float4*>(&E_sh[d * Kc + lane * 4]);
        float4 za = *reinterpret_cast<const float4*>(&zrow[d * 8]);     // broadcast
        float4 zb = *reinterpret_cast<const float4*>(&zrow[d * 8 + 4]); // broadcast
        acc[0][0] = fmaf(za.x, ev.x, acc[0][0]); acc[0][1] = fmaf(za.x, ev.y, acc[0][1]);
        acc[0][2] = fmaf(za.x, ev.z, acc[0][2]); acc[0][3] = fmaf(za.x, ev.w, acc[0][3]);
        acc[1][0] = fmaf(za.y, ev.x, acc[1][0]); acc[1][1] = fmaf(za.y, ev.y, acc[1][1]);
        acc[1][2] = fmaf(za.y, ev.z, acc[1][2]); acc[1][3] = fmaf(za.y, ev.w, acc[1][3]);
        acc[2][0] = fmaf(za.z, ev.x, acc[2][0]); acc[2][1] = fmaf(za.z, ev.y, acc[2][1]);
        acc[2][2] = fmaf(za.z, ev.z, acc[2][2]); acc[2][3] = fmaf(za.z, ev.w, acc[2][3]);
        acc[3][0] = fmaf(za.w, ev.x, acc[3][0]); acc[3][1] = fmaf(za.w, ev.y, acc[3][1]);
        acc[3][2] = fmaf(za.w, ev.z, acc[3][2]); acc[3][3] = fmaf(za.w, ev.w, acc[3][3]);
        acc[4][0] = fmaf(zb.x, ev.x, acc[4][0]); acc[4][1] = fmaf(zb.x, ev.y, acc[4][1]);
        acc[4][2] = fmaf(zb.x, ev.z, acc[4][2]); acc[4][3] = fmaf(zb.x, ev.w, acc[4][3]);
        acc[5][0] = fmaf(zb.y, ev.x, acc[5][0]); acc[5][1] = fmaf(zb.y, ev.y, acc[5][1]);
        acc[5][2] = fmaf(zb.y, ev.z, acc[5][2]); acc[5][3] = fmaf(zb.y, ev.w, acc[5][3]);
        acc[6][0] = fmaf(zb.z, ev.x, acc[6][0]); acc[6][1] = fmaf(zb.z, ev.y, acc[6][1]);
        acc[6][2] = fmaf(zb.z, ev.z, acc[6][2]); acc[6][3] = fmaf(zb.z, ev.w, acc[6][3]);
        acc[7][0] = fmaf(zb.w, ev.x, acc[7][0]); acc[7][1] = fmaf(zb.w, ev.y, acc[7][1]);
        acc[7][2] = fmaf(zb.w, ev.z, acc[7][2]); acc[7][3] = fmaf(zb.w, ev.w, acc[7][3]);
    }

    const float4 e4 = *reinterpret_cast<const float4*>(&e2_sh[lane * 4]);

    int bi_arr[Nn];
#pragma unroll
    for (int n = 0; n < Nn; ++n) {
        const float z2n = z2v[n];
        // dist = fl(fl(z2 - 2*cross) + e2)   (exact jnp order)
        float v0 = __fadd_rn(fmaf(-2.0f, acc[n][0], z2n), e4.x);
        float v1 = __fadd_rn(fmaf(-2.0f, acc[n][1], z2n), e4.y);
        float v2 = __fadd_rn(fmaf(-2.0f, acc[n][2], z2n), e4.z);
        float v3 = __fadd_rn(fmaf(-2.0f, acc[n][3], z2n), e4.w);

        float best = v0; int bi = lane * 4;
        if (v1 < best) { best = v1; bi = lane * 4 + 1; }
        if (v2 < best) { best = v2; bi = lane * 4 + 2; }
        if (v3 < best) { best = v3; bi = lane * 4 + 3; }
#pragma unroll
        for (int off = 16; off > 0; off >>= 1) {
            float ov = __shfl_xor_sync(0xFFFFFFFFu, best, off);
            int   oi = __shfl_xor_sync(0xFFFFFFFFu, bi,  off);
            if (ov < best || (ov == best && oi < bi)) { best = ov; bi = oi; }
        }
        bi_arr[n] = bi;   // all lanes hold the result (butterfly)
    }

    // lane writes positions i = 32t + lane; n = i&7 = lane&7 (constant/lane)
    int bsel = bi_arr[0];
#pragma unroll
    for (int n = 1; n < Nn; ++n)
        if ((lane & 7) == n) bsel = bi_arr[n];

    float* erow = emb + (b0 + s) * H1;
#pragma unroll
    for (int t = 0; t < H1 / 32; ++t) {
        int i = t * 32 + lane;
        erow[i] = E_sh[(i >> 3) * Kc + bsel];
    }
}

// ---------------------------------------------------------------------------
extern "C" void kernel_launch(void* const* d_in, const int* in_sizes, int n_in,
                              void* d_out, int out_size)
{
    const float* x  = (const float*)d_in[0];
    const float* W1 = (const float*)d_in[1];
    const float* b1 = (const float*)d_in[2];
    const float* W2 = (const float*)d_in[3];
    const float* b2 = (const float*)d_in[4];
    const float* W3 = (const float*)d_in[5];
    const float* b3 = (const float*)d_in[6];
    const float* W4 = (const float*)d_in[7];
    const float* b4 = (const float*)d_in[8];
    const float* E  = (const float*)d_in[9];

    float* out   = (float*)d_out;
    float* recon = out;                                   // [B, 784]
    float* z_e   = out + (size_t)Bsz * IN_DIM;            // [B, 1024]
    float* emb   = out + (size_t)Bsz * (IN_DIM + H1);     // [B, 1024] (== z_q)

    void *p_h1, *p_h3;
    cudaGetSymbolAddress(&p_h1, g_h1);
    cudaGetSymbolAddress(&p_h3, g_h3);
    float* h1f = (float*)p_h1;
    float* h3f = (float*)p_h3;

    static bool attr_set = false;
    if (!attr_set) {
        cudaFuncSetAttribute(vq_kernel,
                             cudaFuncAttributeMaxDynamicSharedMemorySize, VQ_SMEM);
        attr_set = true;
    }

    // GEMM1: h1 = relu(x @ W1 + b1)     M=32768 K=784 N=512
    {
        dim3 grid(H0 / 128, Bsz / 128);
        gemm_kernel<1><<<grid, 256>>>(x, W1, b1, h1f, Bsz, H0, IN_DIM);
    }
    // GEMM2: z_e = h1 @ W2 + b2         M=32768 K=512 N=1024
    {
        dim3 grid(H1 / 128, Bsz / 128);
        gemm_kernel<0><<<grid, 256>>>(h1f, W2, b2, z_e, Bsz, H1, H0);
    }
    // Fused VQ: z_e -> emb
    vq_kernel<<<Bsz / VQ_SAMPLES, 256, VQ_SMEM>>>(z_e, E, emb);

    // GEMM3: h3 = relu(emb @ W3 + b3)   M=32768 K=1024 N=512
    {
        dim3 grid(H0 / 128, Bsz / 128);
        gemm_kernel<1><<<grid, 256>>>(emb, W3, b3, h3f, Bsz, H0, H1);
    }
    // GEMM4: recon = tanh(h3 @ W4 + b4) M=32768 K=512 N=784
    {
        dim3 grid((IN_DIM + 127) / 128, Bsz / 128);
        gemm_kernel<2><<<grid, 256>>>(h3f, W4, b4, recon, Bsz, IN_DIM, H0);
    }
}

// round 7
// speedup vs baseline: 1.3375x; 1.3375x over previous
#include <cuda_runtime.h>
#include <cuda_bf16.h>
#include <math.h>

// ---------------------------------------------------------------------------
// VQ-VAE forward on GB300 (sm_103a). Round 4:
//   - GEMM3 eliminated via codebook factorization:
//       P[n,k,j] = sum_d E[d,k] * W3[d*8+n, j]   (2MB table, built once/launch)
//       h3[b,j]  = relu(b3[j] + sum_n P[n, idx[b,n], j])
//   - SGEMM double-buffered (1 sync/k-step), k-order unchanged (argmin-safe).
// Output layout: recon | z_e | emb  (fp32, concatenated)
// ---------------------------------------------------------------------------

#define Bsz    32768
#define IN_DIM 784
#define H0     512
#define H1     1024
#define Kc     128
#define Dd     128
#define Nn     8

// Scratch (__device__ globals; no allocation allowed)
__device__ __align__(16) float g_h1[Bsz * H0];            // 64 MB
__device__ __align__(16) float g_h3[Bsz * H0];            // 64 MB
__device__ __align__(16) float g_P[Nn * Kc * H0];         // 2 MB
__device__ int   g_idx[Bsz * Nn];                         // 1 MB

// ---------------------------------------------------------------------------
// Tiled SGEMM: C[M,N] = act(A[M,K] @ W[K,N] + bias)
// BM=BN=128, BK=8, 256 threads, 8x8 microtile, double-buffered smem.
// Per-element accumulation is strictly k-ascending FFMA (argmin-safe; only
// prefetch timing differs from a single-buffer version). ACT:0=none,1=relu,2=tanh
// ---------------------------------------------------------------------------
template <int ACT>
__global__ __launch_bounds__(256, 2)
void gemm_kernel(const float* __restrict__ A, const float* __restrict__ W,
                 const float* __restrict__ bias, float* __restrict__ C,
                 int M, int N, int K)
{
    __shared__ float As[2][8][128];
    __shared__ float Bs[2][8][128];

    const int tid = threadIdx.x;
    const int m0  = blockIdx.y * 128;
    const int n0  = blockIdx.x * 128;

    const int tx = tid & 15;
    const int ty = tid >> 4;
    const int row0 = ty * 8;
    const int col0 = tx * 8;

    const int a_r = tid >> 1;
    const int a_q = (tid & 1) * 4;
    const int b_r = tid >> 5;
    const int b_q = (tid & 31) * 4;

    const bool b_ok = (n0 + b_q < N);

    float acc[8][8];
#pragma unroll
    for (int i = 0; i < 8; ++i)
#pragma unroll
        for (int j = 0; j < 8; ++j) acc[i][j] = 0.0f;

    const int nsteps = K >> 3;

    // prologue: stage k-step 0 into buffer 0
    float4 av = *reinterpret_cast<const float4*>(&A[(size_t)(m0 + a_r) * K + a_q]);
    float4 bv = make_float4(0.f, 0.f, 0.f, 0.f);
    if (b_ok)
        bv = *reinterpret_cast<const float4*>(&W[(size_t)b_r * N + n0 + b_q]);
    As[0][a_q + 0][a_r] = av.x;
    As[0][a_q + 1][a_r] = av.y;
    As[0][a_q + 2][a_r] = av.z;
    As[0][a_q + 3][a_r] = av.w;
    *reinterpret_cast<float4*>(&Bs[0][b_r][b_q]) = bv;
    __syncthreads();

    for (int s = 0; s < nsteps; ++s) {
        const int cur = s & 1;
        const bool more = (s + 1 < nsteps);

        if (more) {
            const int k0 = (s + 1) << 3;
            av = *reinterpret_cast<const float4*>(
                &A[(size_t)(m0 + a_r) * K + k0 + a_q]);
            if (b_ok)
                bv = *reinterpret_cast<const float4*>(
                    &W[(size_t)(k0 + b_r) * N + n0 + b_q]);
        }

#pragma unroll
        for (int kk = 0; kk < 8; ++kk) {
            float a[8], b[8];
            *reinterpret_cast<float4*>(&a[0]) = *reinterpret_cast<const float4*>(&As[cur][kk][row0]);
            *reinterpret_cast<float4*>(&a[4]) = *reinterpret_cast<const float4*>(&As[cur][kk][row0 + 4]);
            *reinterpret_cast<float4*>(&b[0]) = *reinterpret_cast<const float4*>(&Bs[cur][kk][col0]);
            *reinterpret_cast<float4*>(&b[4]) = *reinterpret_cast<const float4*>(&Bs[cur][kk][col0 + 4]);
#pragma unroll
            for (int i = 0; i < 8; ++i)
#pragma unroll
                for (int j = 0; j < 8; ++j)
                    acc[i][j] = fmaf(a[i], b[j], acc[i][j]);
        }

        if (more) {
            const int nxt = cur ^ 1;
            As[nxt][a_q + 0][a_r] = av.x;
            As[nxt][a_q + 1][a_r] = av.y;
            As[nxt][a_q + 2][a_r] = av.z;
            As[nxt][a_q + 3][a_r] = av.w;
            *reinterpret_cast<float4*>(&Bs[nxt][b_r][b_q]) = bv;
        }
        __syncthreads();
    }

#pragma unroll
    for (int i = 0; i < 8; ++i) {
        const size_t rowoff = (size_t)(m0 + row0 + i) * N;
#pragma unroll
        for (int j = 0; j < 8; ++j) {
            const int n = n0 + col0 + j;
            if (n < N) {
                float c = acc[i][j];
                if (bias) c = __fadd_rn(c, bias[n]);
                if (ACT == 1) c = fmaxf(c, 0.0f);
                if (ACT == 2) c = tanhf(c);
                C[rowoff + n] = c;
            }
        }
    }
}

// ---------------------------------------------------------------------------
// Fused VQ (jax-rounding-replicated; see R3). Also writes g_idx for decode.
// ---------------------------------------------------------------------------
#define VQ_SAMPLES 8
#define VQ_SMEM ((Kc * Dd + VQ_SAMPLES * H1 + Kc) * (int)sizeof(float))

__global__ __launch_bounds__(256, 2)
void vq_kernel(const float* __restrict__ z_e, const float* __restrict__ E,
               float* __restrict__ emb, int* __restrict__ idx_out)
{
    extern __shared__ float sh[];
    float* E_sh  = sh;                       // [Dd][Kc]
    float* z_sh  = sh + Kc * Dd;             // [8][1024]
    float* e2_sh = z_sh + VQ_SAMPLES * H1;   // [Kc]

    const int tid  = threadIdx.x;
    const int warp = tid >> 5;
    const int lane = tid & 31;
    const size_t b0 = (size_t)blockIdx.x * VQ_SAMPLES;

#pragma unroll
    for (int i = 0; i < (Kc * Dd / 4) / 256; ++i)
        reinterpret_cast<float4*>(E_sh)[tid + i * 256] =
            reinterpret_cast<const float4*>(E)[tid + i * 256];
#pragma unroll
    for (int i = 0; i < (VQ_SAMPLES * H1 / 4) / 256; ++i)
        reinterpret_cast<float4*>(z_sh)[tid + i * 256] =
            reinterpret_cast<const float4*>(z_e + b0 * H1)[tid + i * 256];
    __syncthreads();

    // e2[k]: d-ascending, separate mul/add (matches XLA reduce emitter)
    if (tid < Kc) {
        float s = 0.f;
#pragma unroll 16
        for (int d = 0; d < Dd; ++d) {
            float v = E_sh[d * Kc + tid];
            s = __fadd_rn(s, __fmul_rn(v, v));
        }
        e2_sh[tid] = s;
    }
    __syncthreads();

    const int s = warp;
    const float* zrow = z_sh + s * H1;

    // z2[n]: d-ascending, separate mul/add
    float s2 = 0.f;
    {
        const int n = lane & 7;
#pragma unroll 16
        for (int d = 0; d < Dd; ++d) {
            float v = zrow[d * 8 + n];
            s2 = __fadd_rn(s2, __fmul_rn(v, v));
        }
    }
    float z2v[Nn];
#pragma unroll
    for (int n = 0; n < Nn; ++n)
        z2v[n] = __shfl_sync(0xFFFFFFFFu, s2, n);

    // cross: d-ascending FFMA chains
    float acc[Nn][4];
#pragma unroll
    for (int n = 0; n < Nn; ++n)
#pragma unroll
        for (int j = 0; j < 4; ++j) acc[n][j] = 0.f;

#pragma unroll 4
    for (int d = 0; d < Dd; ++d) {
        float4 ev = *reinterpret_cast<const float4*>(&E_sh[d * Kc + lane * 4]);
        float4 za = *reinterpret_cast<const float4*>(&zrow[d * 8]);
        float4 zb = *reinterpret_cast<const float4*>(&zrow[d * 8 + 4]);
        acc[0][0] = fmaf(za.x, ev.x, acc[0][0]); acc[0][1] = fmaf(za.x, ev.y, acc[0][1]);
        acc[0][2] = fmaf(za.x, ev.z, acc[0][2]); acc[0][3] = fmaf(za.x, ev.w, acc[0][3]);
        acc[1][0] = fmaf(za.y, ev.x, acc[1][0]); acc[1][1] = fmaf(za.y, ev.y, acc[1][1]);
        acc[1][2] = fmaf(za.y, ev.z, acc[1][2]); acc[1][3] = fmaf(za.y, ev.w, acc[1][3]);
        acc[2][0] = fmaf(za.z, ev.x, acc[2][0]); acc[2][1] = fmaf(za.z, ev.y, acc[2][1]);
        acc[2][2] = fmaf(za.z, ev.z, acc[2][2]); acc[2][3] = fmaf(za.z, ev.w, acc[2][3]);
        acc[3][0] = fmaf(za.w, ev.x, acc[3][0]); acc[3][1] = fmaf(za.w, ev.y, acc[3][1]);
        acc[3][2] = fmaf(za.w, ev.z, acc[3][2]); acc[3][3] = fmaf(za.w, ev.w, acc[3][3]);
        acc[4][0] = fmaf(zb.x, ev.x, acc[4][0]); acc[4][1] = fmaf(zb.x, ev.y, acc[4][1]);
        acc[4][2] = fmaf(zb.x, ev.z, acc[4][2]); acc[4][3] = fmaf(zb.x, ev.w, acc[4][3]);
        acc[5][0] = fmaf(zb.y, ev.x, acc[5][0]); acc[5][1] = fmaf(zb.y, ev.y, acc[5][1]);
        acc[5][2] = fmaf(zb.y, ev.z, acc[5][2]); acc[5][3] = fmaf(zb.y, ev.w, acc[5][3]);
        acc[6][0] = fmaf(zb.z, ev.x, acc[6][0]); acc[6][1] = fmaf(zb.z, ev.y, acc[6][1]);
        acc[6][2] = fmaf(zb.z, ev.z, acc[6][2]); acc[6][3] = fmaf(zb.z, ev.w, acc[6][3]);
        acc[7][0] = fmaf(zb.w, ev.x, acc[7][0]); acc[7][1] = fmaf(zb.w, ev.y, acc[7][1]);
        acc[7][2] = fmaf(zb.w, ev.z, acc[7][2]); acc[7][3] = fmaf(zb.w, ev.w, acc[7][3]);
    }

    const float4 e4 = *reinterpret_cast<const float4*>(&e2_sh[lane * 4]);

    int bi_arr[Nn];
#pragma unroll
    for (int n = 0; n < Nn; ++n) {
        const float z2n = z2v[n];
        float v0 = __fadd_rn(fmaf(-2.0f, acc[n][0], z2n), e4.x);
        float v1 = __fadd_rn(fmaf(-2.0f, acc[n][1], z2n), e4.y);
        float v2 = __fadd_rn(fmaf(-2.0f, acc[n][2], z2n), e4.z);
        float v3 = __fadd_rn(fmaf(-2.0f, acc[n][3], z2n), e4.w);

        float best = v0; int bi = lane * 4;
        if (v1 < best) { best = v1; bi = lane * 4 + 1; }
        if (v2 < best) { best = v2; bi = lane * 4 + 2; }
        if (v3 < best) { best = v3; bi = lane * 4 + 3; }
#pragma unroll
        for (int off = 16; off > 0; off >>= 1) {
            float ov = __shfl_xor_sync(0xFFFFFFFFu, best, off);
            int   oi = __shfl_xor_sync(0xFFFFFFFFu, bi,  off);
            if (ov < best || (ov == best && oi < bi)) { best = ov; bi = oi; }
        }
        bi_arr[n] = bi;
    }

    // select bi_arr[lane&7] without dynamic indexing
    int bsel = bi_arr[0];
#pragma unroll
    for (int n = 1; n < Nn; ++n)
        if ((lane & 7) == n) bsel = bi_arr[n];

    if (lane < Nn)
        idx_out[(b0 + s) * Nn + lane] = bsel;

    float* erow = emb + (b0 + s) * H1;
#pragma unroll
    for (int t = 0; t < H1 / 32; ++t) {
        int i = t * 32 + lane;
        erow[i] = E_sh[(i >> 3) * Kc + bsel];
    }
}

// ---------------------------------------------------------------------------
// P[n,k,j] = sum_d E[d,k] * W3[d*8+n, j]   (one block per (n,k), 128 thr x 4j)
// ---------------------------------------------------------------------------
__global__ __launch_bounds__(128)
void build_P(const float* __restrict__ E, const float* __restrict__ W3,
             float* __restrict__ P)
{
    const int n = blockIdx.x >> 7;
    const int k = blockIdx.x & 127;
    const int j = threadIdx.x * 4;

    float4 acc = make_float4(0.f, 0.f, 0.f, 0.f);
#pragma unroll 8
    for (int d = 0; d < Dd; ++d) {
        const float e = __ldg(&E[d * Kc + k]);
        const float4 w = *reinterpret_cast<const float4*>(
            &W3[(size_t)(d * 8 + n) * H0 + j]);
        acc.x = fmaf(e, w.x, acc.x);
        acc.y = fmaf(e, w.y, acc.y);
        acc.z = fmaf(e, w.z, acc.z);
        acc.w = fmaf(e, w.w, acc.w);
    }
    *reinterpret_cast<float4*>(&P[((size_t)n * Kc + k) * H0 + j]) = acc;
}

// ---------------------------------------------------------------------------
// h3[b,j] = relu(b3[j] + sum_n P[n, idx[b,n], j])   (replaces GEMM3)
// ---------------------------------------------------------------------------
__global__ __launch_bounds__(128, 8)
void decode_h3(const float* __restrict__ P, const int* __restrict__ idx,
               const float* __restrict__ b3, float* __restrict__ h3)
{
    __shared__ int sid[Nn];
    const int b = blockIdx.x;
    const int tid = threadIdx.x;
    if (tid < Nn) sid[tid] = idx[b * Nn + tid];
    __syncthreads();

    const int j = tid * 4;
    float4 acc = *reinterpret_cast<const float4*>(&b3[j]);
#pragma unroll
    for (int n = 0; n < Nn; ++n) {
        const float4 p = *reinterpret_cast<const float4*>(
            &P[((size_t)n * Kc + sid[n]) * H0 + j]);
        acc.x = __fadd_rn(acc.x, p.x);
        acc.y = __fadd_rn(acc.y, p.y);
        acc.z = __fadd_rn(acc.z, p.z);
        acc.w = __fadd_rn(acc.w, p.w);
    }
    acc.x = fmaxf(acc.x, 0.f);
    acc.y = fmaxf(acc.y, 0.f);
    acc.z = fmaxf(acc.z, 0.f);
    acc.w = fmaxf(acc.w, 0.f);
    *reinterpret_cast<float4*>(&h3[(size_t)b * H0 + j]) = acc;
}

// ---------------------------------------------------------------------------
extern "C" void kernel_launch(void* const* d_in, const int* in_sizes, int n_in,
                              void* d_out, int out_size)
{
    const float* x  = (const float*)d_in[0];
    const float* W1 = (const float*)d_in[1];
    const float* b1 = (const float*)d_in[2];
    const float* W2 = (const float*)d_in[3];
    const float* b2 = (const float*)d_in[4];
    const float* W3 = (const float*)d_in[5];
    const float* b3 = (const float*)d_in[6];
    const float* W4 = (const float*)d_in[7];
    const float* b4 = (const float*)d_in[8];
    const float* E  = (const float*)d_in[9];

    float* out   = (float*)d_out;
    float* recon = out;
    float* z_e   = out + (size_t)Bsz * IN_DIM;
    float* emb   = out + (size_t)Bsz * (IN_DIM + H1);

    void *p_h1, *p_h3, *p_P, *p_idx;
    cudaGetSymbolAddress(&p_h1,  g_h1);
    cudaGetSymbolAddress(&p_h3,  g_h3);
    cudaGetSymbolAddress(&p_P,   g_P);
    cudaGetSymbolAddress(&p_idx, g_idx);
    float* h1f = (float*)p_h1;
    float* h3f = (float*)p_h3;
    float* Pf  = (float*)p_P;
    int*   idxf = (int*)p_idx;

    static bool attr_set = false;
    if (!attr_set) {
        cudaFuncSetAttribute(vq_kernel,
                             cudaFuncAttributeMaxDynamicSharedMemorySize, VQ_SMEM);
        attr_set = true;
    }

    // P table (independent of batch chain; tiny)
    build_P<<<Nn * Kc, 128>>>(E, W3, Pf);

    // GEMM1: h1 = relu(x @ W1 + b1)
    {
        dim3 grid(H0 / 128, Bsz / 128);
        gemm_kernel<1><<<grid, 256>>>(x, W1, b1, h1f, Bsz, H0, IN_DIM);
    }
    // GEMM2: z_e = h1 @ W2 + b2
    {
        dim3 grid(H1 / 128, Bsz / 128);
        gemm_kernel<0><<<grid, 256>>>(h1f, W2, b2, z_e, Bsz, H1, H0);
    }
    // Fused VQ: z_e -> emb, idx
    vq_kernel<<<Bsz / VQ_SAMPLES, 256, VQ_SMEM>>>(z_e, E, emb, idxf);

    // h3 via P-table gather-sum (replaces GEMM3)
    decode_h3<<<Bsz, 128>>>(Pf, idxf, b3, h3f);

    // GEMM4: recon = tanh(h3 @ W4 + b4)
    {
        dim3 grid((IN_DIM + 127) / 128, Bsz / 128);
        gemm_kernel<2><<<grid, 256>>>(h3f, W4, b4, recon, Bsz, IN_DIM, H0);
    }
}